// round 7
// baseline (speedup 1.0000x reference)
#include <cuda_runtime.h>
#include <cstdint>

// GroupedEmbeddingBag: T tables, weights [V, D] fp32.
// values: [T, L] int32, offsets: [T, B+1] int32, out: [B, T*D] fp32.
// One warp per (table, bag). Rows staged global->smem with cp.async.
// Pipeline depth NG=4 commit groups x G=4 rows: while consuming group k,
// groups k+1..k+3 (12 rows) are in flight. Ring of R=16 slots per warp;
// group k+4 reuses k's slots and is issued only after k is consumed.

static constexpr int T = 8;
static constexpr int V = 100000;
static constexpr int D = 128;
static constexpr int B = 4096;

static constexpr int WARPS_PER_BLOCK = 4;
static constexpr int G  = 4;    // rows per commit group
static constexpr int NG = 4;    // groups in flight
static constexpr int R  = G * NG;  // 16 ring slots per warp (8 KB)

__device__ __forceinline__ void cp_async16(float4* smem_dst, const float* gsrc) {
    uint32_t s = (uint32_t)__cvta_generic_to_shared(smem_dst);
    asm volatile("cp.async.cg.shared.global [%0], [%1], 16;\n"
                 :: "r"(s), "l"(gsrc));
}

__global__ void __launch_bounds__(128)
grouped_embedding_bag_kernel(const int* __restrict__ values,
                             const int* __restrict__ offsets,
                             const float* __restrict__ weights,
                             float* __restrict__ out,
                             int L)
{
    __shared__ float4 stage[WARPS_PER_BLOCK][R][32];   // 32 KB / block

    const int warp   = (blockIdx.x * blockDim.x + threadIdx.x) >> 5;
    const int wlocal = (threadIdx.x >> 5);
    const int lane   = threadIdx.x & 31;
    if (warp >= T * B) return;

    // Table-major: consecutive warps share a table -> L2 reuse (~2x).
    const int t = warp / B;
    const int b = warp - t * B;

    const int s = offsets[t * (B + 1) + b];
    const int e = offsets[t * (B + 1) + b + 1];
    const int n = e - s;

    const int*   vals = values + t * L + s;
    const float* Wt   = weights + (long long)t * V * D;

    float4* ring = &stage[wlocal][0][0];   // [R][32] float4

    // Issue one commit group covering rows [g0, g0+G).
    // Empty/partial groups still commit to keep group accounting constant.
    auto issue_group = [&](int g0) {
        #pragma unroll
        for (int j = 0; j < G; j++) {
            const int row = g0 + j;
            if (row < n) {
                const int idx = vals[row];
                cp_async16(&ring[(row & (R - 1)) * 32 + lane],
                           Wt + (long long)idx * D + lane * 4);
            }
        }
        asm volatile("cp.async.commit_group;\n" ::: "memory");
    };

    float4 acc = make_float4(0.f, 0.f, 0.f, 0.f);

    // Prologue: NG groups in flight.
    #pragma unroll
    for (int g = 0; g < NG; g++) issue_group(g * G);

    const int total_groups = (n + G - 1) / G;
    for (int gi = 0; gi < total_groups; gi++) {
        // Allow the NG-1 newest groups to remain pending -> group gi landed.
        asm volatile("cp.async.wait_group %0;\n" :: "n"(NG - 1) : "memory");

        const int g0 = gi * G;
        #pragma unroll
        for (int j = 0; j < G; j++) {
            const int row = g0 + j;
            if (row < n) {
                const float4 r = ring[(row & (R - 1)) * 32 + lane];
                acc.x += r.x; acc.y += r.y; acc.z += r.z; acc.w += r.w;
            }
        }

        // Refill the slots just drained (group may be empty past the end).
        issue_group(g0 + NG * G);
    }

    // out[b, t*D ...]: warp writes 512B contiguous, coalesced.
    float4* dst = reinterpret_cast<float4*>(out + (long long)b * (T * D) + t * D);
    dst[lane] = acc;
}

extern "C" void kernel_launch(void* const* d_in, const int* in_sizes, int n_in,
                              void* d_out, int out_size)
{
    const int*   values  = (const int*)d_in[0];    // [T, L] int32
    const int*   offsets = (const int*)d_in[1];    // [T, B+1] int32
    const float* weights = (const float*)d_in[2];  // [T, V, D] fp32
    float* out = (float*)d_out;                    // [B, T*D] fp32

    const int L = in_sizes[0] / T;

    const int total_warps = T * B;                 // 32768
    const int threads = WARPS_PER_BLOCK * 32;      // 128
    const int blocks = (total_warps * 32 + threads - 1) / threads;  // 8192

    grouped_embedding_bag_kernel<<<blocks, threads>>>(values, offsets, weights, out, L);
}

// round 9
// speedup vs baseline: 1.1899x; 1.1899x over previous
#include <cuda_runtime.h>
#include <cstdint>

// GroupedEmbeddingBag: T tables, weights [V, D] fp32.
// values: [T, L] int32, offsets: [T, B+1] int32, out: [B, T*D] fp32.
// One BLOCK (4 warps) per (table, bag): each warp sums a contiguous quarter
// of the bag's rows (balanced by construction), then a 2 KB smem reduction
// combines the four partials. Gather engine: MLP=8 register prefetch,
// 32 lanes x float4 = one 512B row per load.

static constexpr int T = 8;
static constexpr int V = 100000;
static constexpr int D = 128;
static constexpr int B = 4096;

__global__ void __launch_bounds__(128)
grouped_embedding_bag_kernel(const int* __restrict__ values,
                             const int* __restrict__ offsets,
                             const float* __restrict__ weights,
                             float* __restrict__ out,
                             int L)
{
    __shared__ float4 red[3][32];   // partials from warps 1..3

    const int bag  = blockIdx.x;         // 0 .. T*B-1, table-major
    const int q    = threadIdx.x >> 5;   // warp within block: quarter id
    const int lane = threadIdx.x & 31;

    const int t = bag / B;
    const int b = bag - t * B;

    const int s = offsets[t * (B + 1) + b];
    const int e = offsets[t * (B + 1) + b + 1];
    const int len = e - s;

    // Contiguous quarter [qs, qe) of this bag's rows.
    const int qs = s + ((len * q) >> 2);
    const int qe = s + ((len * (q + 1)) >> 2);

    const int* vals = values + t * L;
    const float4* __restrict__ W =
        reinterpret_cast<const float4*>(weights + (long long)t * V * D);

    float4 acc0 = make_float4(0.f, 0.f, 0.f, 0.f);
    float4 acc1 = make_float4(0.f, 0.f, 0.f, 0.f);

    int i = qs;

    // Main loop: 8 independent row gathers in flight.
    for (; i + 8 <= qe; i += 8) {
        int idx[8];
        #pragma unroll
        for (int j = 0; j < 8; j++) idx[j] = vals[i + j];

        float4 r[8];
        #pragma unroll
        for (int j = 0; j < 8; j++)
            r[j] = __ldg(&W[(long long)idx[j] * 32 + lane]);

        #pragma unroll
        for (int j = 0; j < 8; j += 2) {
            acc0.x += r[j].x;     acc0.y += r[j].y;
            acc0.z += r[j].z;     acc0.w += r[j].w;
            acc1.x += r[j + 1].x; acc1.y += r[j + 1].y;
            acc1.z += r[j + 1].z; acc1.w += r[j + 1].w;
        }
    }

    // Remainder (< 8 rows), still issuing independent loads.
    {
        int idx[8];
        const int n = qe - i;
        #pragma unroll
        for (int j = 0; j < 8; j++)
            idx[j] = (j < n) ? vals[i + j] : -1;

        float4 r[8];
        #pragma unroll
        for (int j = 0; j < 8; j++)
            if (idx[j] >= 0)
                r[j] = __ldg(&W[(long long)idx[j] * 32 + lane]);

        #pragma unroll
        for (int j = 0; j < 8; j++)
            if (idx[j] >= 0) {
                acc0.x += r[j].x; acc0.y += r[j].y;
                acc0.z += r[j].z; acc0.w += r[j].w;
            }
    }

    acc0.x += acc1.x; acc0.y += acc1.y; acc0.z += acc1.z; acc0.w += acc1.w;

    // Combine the four quarter-partials.
    if (q > 0) red[q - 1][lane] = acc0;
    __syncthreads();

    if (q == 0) {
        #pragma unroll
        for (int w = 0; w < 3; w++) {
            const float4 p = red[w][lane];
            acc0.x += p.x; acc0.y += p.y; acc0.z += p.z; acc0.w += p.w;
        }
        // out[b, t*D ...]: 512B contiguous, coalesced.
        float4* dst = reinterpret_cast<float4*>(out + (long long)b * (T * D) + t * D);
        dst[lane] = acc0;
    }
}

extern "C" void kernel_launch(void* const* d_in, const int* in_sizes, int n_in,
                              void* d_out, int out_size)
{
    const int*   values  = (const int*)d_in[0];    // [T, L] int32
    const int*   offsets = (const int*)d_in[1];    // [T, B+1] int32
    const float* weights = (const float*)d_in[2];  // [T, V, D] fp32
    float* out = (float*)d_out;                    // [B, T*D] fp32

    const int L = in_sizes[0] / T;

    const int blocks  = T * B;   // 32768 blocks, one bag each
    const int threads = 128;     // 4 warps = 4 quarters

    grouped_embedding_bag_kernel<<<blocks, threads>>>(values, offsets, weights, out, L);
}

// round 10
// speedup vs baseline: 1.1914x; 1.0013x over previous
#include <cuda_runtime.h>
#include <cstdint>

// GroupedEmbeddingBag: T tables, weights [V, D] fp32.
// values: [T, L] int32, offsets: [T, B+1] int32, out: [B, T*D] fp32.
// One BLOCK (4 warps) per (table, bag); warp q sums a contiguous quarter of
// the bag's rows, then a 2 KB smem reduction combines partials.
// Index fetch: ONE coalesced LDG.32 per 32 rows (lane i reads vals[c+i]),
// indices broadcast to the warp via __shfl_sync -> gathers issue in batches
// of 8 with no per-row memory dependency. Tail batches clamp the shfl source
// and mask the accumulate so they still get 8-wide MLP.

static constexpr int T = 8;
static constexpr int V = 100000;
static constexpr int D = 128;
static constexpr int B = 4096;

__global__ void __launch_bounds__(128)
grouped_embedding_bag_kernel(const int* __restrict__ values,
                             const int* __restrict__ offsets,
                             const float* __restrict__ weights,
                             float* __restrict__ out,
                             int L)
{
    __shared__ float4 red[3][32];   // partials from warps 1..3

    const int bag  = blockIdx.x;         // 0 .. T*B-1, table-major
    const int q    = threadIdx.x >> 5;   // warp within block: quarter id
    const int lane = threadIdx.x & 31;

    const int t = bag / B;
    const int b = bag - t * B;

    const int s = offsets[t * (B + 1) + b];
    const int e = offsets[t * (B + 1) + b + 1];
    const int len = e - s;

    // Contiguous quarter [qs, qe) of this bag's rows.
    const int qs = s + ((len * q) >> 2);
    const int qe = s + ((len * (q + 1)) >> 2);

    const int* vals = values + t * L;
    const float4* __restrict__ W =
        reinterpret_cast<const float4*>(weights + (long long)t * V * D);

    float4 acc0 = make_float4(0.f, 0.f, 0.f, 0.f);
    float4 acc1 = make_float4(0.f, 0.f, 0.f, 0.f);

    int i = qs;
    while (i < qe) {
        const int m = min(32, qe - i);
        // One coalesced index load covers up to 32 rows.
        const int myidx = (lane < m) ? vals[i + lane] : 0;

        for (int j = 0; j < m; j += 8) {
            float4 r[8];
            #pragma unroll
            for (int k = 0; k < 8; k++) {
                const int src = (j + k < m) ? (j + k) : (m - 1);   // clamp tail
                const int idx = __shfl_sync(0xffffffffu, myidx, src);
                r[k] = __ldg(&W[(long long)idx * 32 + lane]);
            }
            #pragma unroll
            for (int k = 0; k < 8; k += 2) {
                if (j + k < m) {
                    acc0.x += r[k].x; acc0.y += r[k].y;
                    acc0.z += r[k].z; acc0.w += r[k].w;
                }
                if (j + k + 1 < m) {
                    acc1.x += r[k + 1].x; acc1.y += r[k + 1].y;
                    acc1.z += r[k + 1].z; acc1.w += r[k + 1].w;
                }
            }
        }
        i += m;
    }

    acc0.x += acc1.x; acc0.y += acc1.y; acc0.z += acc1.z; acc0.w += acc1.w;

    // Combine the four quarter-partials.
    if (q > 0) red[q - 1][lane] = acc0;
    __syncthreads();

    if (q == 0) {
        #pragma unroll
        for (int w = 0; w < 3; w++) {
            const float4 p = red[w][lane];
            acc0.x += p.x; acc0.y += p.y; acc0.z += p.z; acc0.w += p.w;
        }
        // out[b, t*D ...]: 512B contiguous, coalesced.
        float4* dst = reinterpret_cast<float4*>(out + (long long)b * (T * D) + t * D);
        dst[lane] = acc0;
    }
}

extern "C" void kernel_launch(void* const* d_in, const int* in_sizes, int n_in,
                              void* d_out, int out_size)
{
    const int*   values  = (const int*)d_in[0];    // [T, L] int32
    const int*   offsets = (const int*)d_in[1];    // [T, B+1] int32
    const float* weights = (const float*)d_in[2];  // [T, V, D] fp32
    float* out = (float*)d_out;                    // [B, T*D] fp32

    const int L = in_sizes[0] / T;

    const int blocks  = T * B;   // 32768 blocks, one bag each
    const int threads = 128;     // 4 warps = 4 quarters

    grouped_embedding_bag_kernel<<<blocks, threads>>>(values, offsets, weights, out, L);
}

// round 11
// speedup vs baseline: 1.2072x; 1.0132x over previous
#include <cuda_runtime.h>
#include <cstdint>

// GroupedEmbeddingBag: T tables, weights [V, D] fp32.
// values: [T, L] int32, offsets: [T, B+1] int32, out: [B, T*D] fp32.
// One BLOCK (4 warps) per (table, bag); warp q sums a contiguous quarter,
// then a 2 KB smem reduction combines partials.
// Occupancy-tuned: batch=6 gathers, 32-bit offsets, L1::no_allocate loads,
// __launch_bounds__(128,10) -> target 48 regs = 10 blocks/SM = 40 warps.
// Index fetch: one coalesced LDG.32 per 24 rows, shfl-broadcast to the warp.

static constexpr int T = 8;
static constexpr int V = 100000;
static constexpr int D = 128;
static constexpr int B = 4096;

__device__ __forceinline__ float4 ldg_na(const void* p) {
    float4 v;
    asm volatile("ld.global.nc.L1::no_allocate.v4.f32 {%0,%1,%2,%3}, [%4];"
                 : "=f"(v.x), "=f"(v.y), "=f"(v.z), "=f"(v.w)
                 : "l"(p));
    return v;
}

__global__ void __launch_bounds__(128, 10)
grouped_embedding_bag_kernel(const int* __restrict__ values,
                             const int* __restrict__ offsets,
                             const float* __restrict__ weights,
                             float* __restrict__ out,
                             int L)
{
    __shared__ float4 red[3][32];   // partials from warps 1..3

    const int bag  = blockIdx.x;         // 0 .. T*B-1, table-major
    const int q    = threadIdx.x >> 5;   // warp within block: quarter id
    const int lane = threadIdx.x & 31;

    const int t = bag / B;
    const int b = bag - t * B;

    const int s = offsets[t * (B + 1) + b];
    const int e = offsets[t * (B + 1) + b + 1];
    const int len = e - s;

    // Contiguous quarter [qs, qe) of this bag's rows.
    const int qs = s + ((len * q) >> 2);
    const int qe = s + ((len * (q + 1)) >> 2);

    const int* vals = values + t * L;
    // Per-table base; per-row offset fits in 32 bits (idx*512 <= 51.2 MB).
    const char* __restrict__ Wb =
        reinterpret_cast<const char*>(weights + (long long)t * V * D);
    const unsigned lane_off = (unsigned)lane * 16u;

    float4 acc0 = make_float4(0.f, 0.f, 0.f, 0.f);
    float4 acc1 = make_float4(0.f, 0.f, 0.f, 0.f);

    int i = qs;
    while (i < qe) {
        const int m = min(24, qe - i);
        // One coalesced index load covers up to 24 rows (lanes 0..23).
        const int myidx = (lane < m) ? vals[i + lane] : 0;

        for (int j = 0; j < m; j += 6) {
            float4 r[6];
            #pragma unroll
            for (int k = 0; k < 6; k++) {
                const int src = (j + k < m) ? (j + k) : (m - 1);   // clamp tail
                const unsigned idx =
                    (unsigned)__shfl_sync(0xffffffffu, myidx, src);
                r[k] = ldg_na(Wb + idx * 512u + lane_off);
            }
            #pragma unroll
            for (int k = 0; k < 6; k += 2) {
                if (j + k < m) {
                    acc0.x += r[k].x; acc0.y += r[k].y;
                    acc0.z += r[k].z; acc0.w += r[k].w;
                }
                if (j + k + 1 < m) {
                    acc1.x += r[k + 1].x; acc1.y += r[k + 1].y;
                    acc1.z += r[k + 1].z; acc1.w += r[k + 1].w;
                }
            }
        }
        i += m;
    }

    acc0.x += acc1.x; acc0.y += acc1.y; acc0.z += acc1.z; acc0.w += acc1.w;

    // Combine the four quarter-partials.
    if (q > 0) red[q - 1][lane] = acc0;
    __syncthreads();

    if (q == 0) {
        #pragma unroll
        for (int w = 0; w < 3; w++) {
            const float4 p = red[w][lane];
            acc0.x += p.x; acc0.y += p.y; acc0.z += p.z; acc0.w += p.w;
        }
        // out[b, t*D ...]: 512B contiguous, coalesced.
        float4* dst = reinterpret_cast<float4*>(out + (long long)b * (T * D) + t * D);
        dst[lane] = acc0;
    }
}

extern "C" void kernel_launch(void* const* d_in, const int* in_sizes, int n_in,
                              void* d_out, int out_size)
{
    const int*   values  = (const int*)d_in[0];    // [T, L] int32
    const int*   offsets = (const int*)d_in[1];    // [T, B+1] int32
    const float* weights = (const float*)d_in[2];  // [T, V, D] fp32
    float* out = (float*)d_out;                    // [B, T*D] fp32

    const int L = in_sizes[0] / T;

    const int blocks  = T * B;   // 32768 blocks, one bag each
    const int threads = 128;     // 4 warps = 4 quarters

    grouped_embedding_bag_kernel<<<blocks, threads>>>(values, offsets, weights, out, L);
}

// round 12
// speedup vs baseline: 1.2437x; 1.0303x over previous
#include <cuda_runtime.h>
#include <cstdint>

// GroupedEmbeddingBag: T tables, weights [V, D] fp32.
// values: [T, L] int32, offsets: [T, B+1] int32, out: [B, T*D] fp32.
// One WARP = one whole bag, launched as 32-thread CTAs so resources free
// the instant a bag finishes (no sibling-warp imbalance). Registers are
// free at 1 warp/CTA (2048/warp) -> double-buffered gather pipeline:
// issue batch k+1 (8 rows) before consuming batch k, so 8-16 rows stay in
// flight for the bag's whole lifetime. Indices for 64 rows are loaded with
// two coalesced LDG.32s at chunk start and shfl-broadcast.

static constexpr int T = 8;
static constexpr int V = 100000;
static constexpr int D = 128;
static constexpr int B = 4096;

__device__ __forceinline__ float4 ldg_na(const void* p) {
    float4 v;
    asm volatile("ld.global.nc.L1::no_allocate.v4.f32 {%0,%1,%2,%3}, [%4];"
                 : "=f"(v.x), "=f"(v.y), "=f"(v.z), "=f"(v.w)
                 : "l"(p));
    return v;
}

__global__ void __launch_bounds__(32)
grouped_embedding_bag_kernel(const int* __restrict__ values,
                             const int* __restrict__ offsets,
                             const float* __restrict__ weights,
                             float* __restrict__ out,
                             int L)
{
    const int bag  = blockIdx.x;       // 0 .. T*B-1, table-major
    const int lane = threadIdx.x;

    const int t = bag / B;
    const int b = bag - t * B;

    const int s = offsets[t * (B + 1) + b];
    const int e = offsets[t * (B + 1) + b + 1];

    const int* vals = values + t * L;
    // Per-table base; per-row byte offset fits in 32 bits (idx*512 <= 51.2MB).
    const char* __restrict__ Wb =
        reinterpret_cast<const char*>(weights + (long long)t * V * D);
    const unsigned lane_off = (unsigned)lane * 16u;

    float4 acc0 = make_float4(0.f, 0.f, 0.f, 0.f);
    float4 acc1 = make_float4(0.f, 0.f, 0.f, 0.f);

    int i = s;
    while (i < e) {
        const int m = min(64, e - i);          // 64-row chunk
        // Two coalesced index loads, issued together (one latency window).
        const int my0 = (lane      < m) ? vals[i + lane]      : 0;
        const int my1 = (lane + 32 < m) ? vals[i + lane + 32] : 0;

        // idx for chunk-row r (clamped to m-1 for tail duplicates).
        auto get_idx = [&](int r) -> unsigned {
            const int rc  = (r < m) ? r : (m - 1);
            const int v32 = (rc < 32) ? my0 : my1;
            return (unsigned)__shfl_sync(0xffffffffu, v32, rc & 31);
        };
        auto gather8 = [&](float4* buf, int j) {
            #pragma unroll
            for (int k = 0; k < 8; k++)
                buf[k] = ldg_na(Wb + get_idx(j + k) * 512u + lane_off);
        };
        auto consume8 = [&](const float4* buf, int j) {
            #pragma unroll
            for (int k = 0; k < 8; k += 2) {
                if (j + k < m) {
                    acc0.x += buf[k].x; acc0.y += buf[k].y;
                    acc0.z += buf[k].z; acc0.w += buf[k].w;
                }
                if (j + k + 1 < m) {
                    acc1.x += buf[k+1].x; acc1.y += buf[k+1].y;
                    acc1.z += buf[k+1].z; acc1.w += buf[k+1].w;
                }
            }
        };

        float4 bufA[8], bufB[8];
        gather8(bufA, 0);
        for (int j = 0; j < m; j += 16) {
            if (j + 8 < m)  gather8(bufB, j + 8);
            consume8(bufA, j);
            if (j + 16 < m) gather8(bufA, j + 16);
            if (j + 8 < m)  consume8(bufB, j + 8);
        }
        i += m;
    }

    acc0.x += acc1.x; acc0.y += acc1.y; acc0.z += acc1.z; acc0.w += acc1.w;

    // out[b, t*D ...]: 512B contiguous, coalesced. Empty bags write zeros.
    float4* dst = reinterpret_cast<float4*>(out + (long long)b * (T * D) + t * D);
    dst[lane] = acc0;
}

extern "C" void kernel_launch(void* const* d_in, const int* in_sizes, int n_in,
                              void* d_out, int out_size)
{
    const int*   values  = (const int*)d_in[0];    // [T, L] int32
    const int*   offsets = (const int*)d_in[1];    // [T, B+1] int32
    const float* weights = (const float*)d_in[2];  // [T, V, D] fp32
    float* out = (float*)d_out;                    // [B, T*D] fp32

    const int L = in_sizes[0] / T;

    const int blocks  = T * B;   // 32768 one-warp blocks, one bag each
    const int threads = 32;

    grouped_embedding_bag_kernel<<<blocks, threads>>>(values, offsets, weights, out, L);
}